// round 7
// baseline (speedup 1.0000x reference)
#include <cuda_runtime.h>
#include <cuda_bf16.h>
#include <cstdint>

// ---------------------------------------------------------------------------
// SPMoEAdaptor: out = moe_b(moe_a(x)) + x
//   moe(x) = sum_e softmax(x@Wg)[:,e] * ((x - b_e) @ W_e)
//          = sum_e (g_e * x) @ W_e  -  sum_e g_e * (b_e @ W_e)
// R6: same math/dataflow as R5 (n-major weights, non-trans ldmatrix, tensor-
// core gates, folded bias/residual, streaming stores) but 256-thread CTAs
// with __launch_bounds__(256,2): occupancy was register-bound (3x128x168 =
// 64K RF); 2 CTAs x 256 thr @ <=128 regs gives 16 warps/SM (+33%) and halves
// the per-warp share of the one-time weight copy.
// ---------------------------------------------------------------------------

namespace {
constexpr int MT = 256;                 // tokens per tile (32 per warp, 8 warps)

// dynamic smem layout (bytes)
constexpr int SM_WA  = 0;               // 64 rows x 512B bf16 (layer A W^T, swizzled)
constexpr int SM_WB  = 32768;           // layer B weights
constexpr int SM_WGA = 65536;           // 64 x float4 (w_gate_a as [d][e])
constexpr int SM_WGB = 66560;
constexpr int SM_CA  = 67584;           // 64 x float4 (c_a as [f][e])
constexpr int SM_CB  = 68608;
constexpr int SMEM_TOTAL = 69632;       // 68KB -> 2 CTAs/SM (136KB)

constexpr int GRID = 296;               // 148 SMs * 2 CTAs/SM
}

// device-global scratch (allocation-free rule)
// n-major: row f (0..63), 256 bf16 per row (k = e*64+d), chunk-XOR swizzled.
__device__ __align__(16) __nv_bfloat16 g_wswz[2][64 * 256];
__device__ __align__(16) float g_c[2][64 * 4];   // c[L][f*4+e] = (b_e @ W_e)[f]

// ------------------------------- helpers ----------------------------------

__device__ __forceinline__ uint32_t smem_u32(const void* p) {
    uint32_t a;
    asm("{ .reg .u64 t; cvta.to.shared.u64 t, %1; cvt.u32.u64 %0, t; }" : "=r"(a) : "l"(p));
    return a;
}

__device__ __forceinline__ void ldsm_x4(uint32_t* r, uint32_t addr) {
    asm volatile("ldmatrix.sync.aligned.m8n8.x4.shared.b16 {%0,%1,%2,%3}, [%4];"
                 : "=r"(r[0]), "=r"(r[1]), "=r"(r[2]), "=r"(r[3]) : "r"(addr));
}

__device__ __forceinline__ void mma_bf16(float* d, const uint32_t* a,
                                         uint32_t b0, uint32_t b1) {
    asm volatile("mma.sync.aligned.m16n8k16.row.col.f32.bf16.bf16.f32 "
                 "{%0,%1,%2,%3}, {%4,%5,%6,%7}, {%8,%9}, {%0,%1,%2,%3};"
                 : "+f"(d[0]), "+f"(d[1]), "+f"(d[2]), "+f"(d[3])
                 : "r"(a[0]), "r"(a[1]), "r"(a[2]), "r"(a[3]), "r"(b0), "r"(b1));
}

__device__ __forceinline__ uint32_t pack_bf2(float lo, float hi) {
    __nv_bfloat162 t = __floats2bfloat162_rn(lo, hi);
    return *reinterpret_cast<uint32_t*>(&t);
}

__device__ __forceinline__ uint32_t bf2bcast(float v) { return pack_bf2(v, v); }

__device__ __forceinline__ uint32_t hmul2u(uint32_t a, uint32_t b) {
    __nv_bfloat162 r = __hmul2(*reinterpret_cast<__nv_bfloat162*>(&a),
                               *reinterpret_cast<__nv_bfloat162*>(&b));
    return *reinterpret_cast<uint32_t*>(&r);
}

__device__ __forceinline__ float dot4(float4 a, float4 b) {
    return a.x * b.x + a.y * b.y + a.z * b.z + a.w * b.w;
}

__device__ __forceinline__ float4 softmax4(float4 l) {
    float mx = fmaxf(fmaxf(l.x, l.y), fmaxf(l.z, l.w));
    float e0 = __expf(l.x - mx), e1 = __expf(l.y - mx),
          e2 = __expf(l.z - mx), e3 = __expf(l.w - mx);
    float inv = 1.f / (e0 + e1 + e2 + e3);
    return make_float4(e0 * inv, e1 * inv, e2 * inv, e3 * inv);
}

// one MoE GEMM layer: acc[2][8][4] += sum over e,kt of (g_e o A_frag) @ W_frag
// Weights n-major: lane address = base + f_local*512 + ((e*8+kt*2+kh)^l7)*16
// + np*8192;  ldsm.x4 (non-trans) yields the mma.row.col B-fragments directly.
__device__ __forceinline__ void run_layer(float acc[2][8][4],
                                          const uint32_t xf[2][4][4],
                                          const uint32_t g2[4][2][2],
                                          uint32_t wbase, int lane) {
    const int l7 = lane & 7;
    const uint32_t lane_row = (uint32_t)(((lane >> 4) & 1) * 8 + l7);  // f within n16 grp
    const uint32_t kh = (uint32_t)((lane >> 3) & 1);                   // k-half
    const uint32_t lane_base = wbase + lane_row * 512u;
    #pragma unroll
    for (int e = 0; e < 4; e++) {
        #pragma unroll
        for (int kt = 0; kt < 4; kt++) {
            uint32_t a[2][4];
            #pragma unroll
            for (int m = 0; m < 2; m++) {
                a[m][0] = hmul2u(xf[m][kt][0], g2[e][m][0]);
                a[m][1] = hmul2u(xf[m][kt][1], g2[e][m][1]);
                a[m][2] = hmul2u(xf[m][kt][2], g2[e][m][0]);
                a[m][3] = hmul2u(xf[m][kt][3], g2[e][m][1]);
            }
            const uint32_t c0 = (uint32_t)(e * 8 + kt * 2) + kh;
            const uint32_t coff = ((c0 ^ (uint32_t)l7) << 4);
            #pragma unroll
            for (int np = 0; np < 4; np++) {
                uint32_t b[4];
                ldsm_x4(b, lane_base + (uint32_t)np * 8192u + coff);
                #pragma unroll
                for (int m = 0; m < 2; m++) {
                    mma_bf16(acc[m][2 * np],     a[m], b[0], b[1]);
                    mma_bf16(acc[m][2 * np + 1], a[m], b[2], b[3]);
                }
            }
        }
    }
}

// gates from A-fragments via tensor core: logits = frag @ Wg (Wg frags const).
// Output cols 0..3 = experts; cols 4..7 duplicate them, so a single
// shfl_xor(1) completes the per-row gather. Two independent accumulator
// chains halve the serial MMA dependency depth.
__device__ __forceinline__ void gates_from_frags(const uint32_t xf[4][4],
                                                 const uint32_t* wg0,
                                                 const uint32_t* wg1,
                                                 int ql,
                                                 float4 gf[2],
                                                 uint32_t g2[4][2]) {
    float l[4]  = {0.f, 0.f, 0.f, 0.f};
    float l2[4] = {0.f, 0.f, 0.f, 0.f};
    mma_bf16(l,  xf[0], wg0[0], wg1[0]);
    mma_bf16(l2, xf[1], wg0[1], wg1[1]);
    mma_bf16(l,  xf[2], wg0[2], wg1[2]);
    mma_bf16(l2, xf[3], wg0[3], wg1[3]);
    l[0] += l2[0]; l[1] += l2[1]; l[2] += l2[2]; l[3] += l2[3];
    float r0 = __shfl_xor_sync(0xffffffffu, l[0], 1);
    float r1 = __shfl_xor_sync(0xffffffffu, l[1], 1);
    float r2 = __shfl_xor_sync(0xffffffffu, l[2], 1);
    float r3 = __shfl_xor_sync(0xffffffffu, l[3], 1);
    bool even = (ql & 1) == 0;
    float4 La = even ? make_float4(l[0], l[1], r0, r1)
                     : make_float4(r0, r1, l[0], l[1]);
    float4 Lb = even ? make_float4(l[2], l[3], r2, r3)
                     : make_float4(r2, r3, l[2], l[3]);
    float4 ga = softmax4(La);
    float4 gb = softmax4(Lb);
    gf[0] = ga; gf[1] = gb;
    g2[0][0] = bf2bcast(ga.x); g2[1][0] = bf2bcast(ga.y);
    g2[2][0] = bf2bcast(ga.z); g2[3][0] = bf2bcast(ga.w);
    g2[0][1] = bf2bcast(gb.x); g2[1][1] = bf2bcast(gb.y);
    g2[2][1] = bf2bcast(gb.z); g2[3][1] = bf2bcast(gb.w);
}

// ------------------------------- prep kernel ------------------------------

__global__ void prep_kernel(const float* __restrict__ wea, const float* __restrict__ bea,
                            const float* __restrict__ web, const float* __restrict__ beb) {
    int idx = blockIdx.x * blockDim.x + threadIdx.x;
    if (idx < 2 * 4 * 64 * 64) {
        int L = idx >> 14;
        int r = idx & 16383;
        int e = r >> 12;
        int d = (r >> 6) & 63;
        int f = r & 63;
        const float* w = L ? web : wea;
        float v = w[(e * 64 + d) * 64 + f];
        // n-major: row f, k = e*64+d; 16B chunk = e*8 + d/8, XOR-swizzled by f&7
        int chunk = (e * 8 + (d >> 3)) ^ (f & 7);
        g_wswz[L][f * 256 + chunk * 8 + (d & 7)] = __float2bfloat16(v);
    }
    if (idx < 2 * 4 * 64) {
        int L = idx >> 8;
        int e = (idx >> 6) & 3;
        int f = idx & 63;
        const float* w = L ? web : wea;
        const float* b = L ? beb : bea;
        float s = 0.f;
        for (int d = 0; d < 64; d++)
            s += b[e * 64 + d] * w[(e * 64 + d) * 64 + f];
        g_c[L][f * 4 + e] = s;
    }
}

// ------------------------------- main kernel ------------------------------

__global__ void __launch_bounds__(256, 2)
moe_kernel(const float* __restrict__ x,
           const float* __restrict__ wg_a,
           const float* __restrict__ wg_b,
           float* __restrict__ out,
           int ntiles) {
    extern __shared__ char smem[];
    const uint32_t sb = smem_u32(smem);
    const int tid  = threadIdx.x;
    const int lane = tid & 31;
    const int warp = tid >> 5;          // 0..7
    const int rbase = warp * 32;

    // ---- one-time cooperative weight copies ----
    {
        const uint4* s0 = reinterpret_cast<const uint4*>(g_wswz[0]);
        const uint4* s1 = reinterpret_cast<const uint4*>(g_wswz[1]);
        uint4* dA = reinterpret_cast<uint4*>(smem + SM_WA);
        uint4* dB = reinterpret_cast<uint4*>(smem + SM_WB);
        #pragma unroll
        for (int i = tid; i < 2048; i += 256) { dA[i] = s0[i]; dB[i] = s1[i]; }
        float* wga_s = reinterpret_cast<float*>(smem + SM_WGA);
        float* wgb_s = reinterpret_cast<float*>(smem + SM_WGB);
        float* ca_s  = reinterpret_cast<float*>(smem + SM_CA);
        float* cb_s  = reinterpret_cast<float*>(smem + SM_CB);
        if (tid < 256) {
            wga_s[tid] = wg_a[tid]; wgb_s[tid] = wg_b[tid];
            ca_s[tid]  = g_c[0][tid]; cb_s[tid] = g_c[1][tid];
        }
    }
    __syncthreads();

    const float4* CA4  = reinterpret_cast<const float4*>(smem + SM_CA);
    const float4* CB4  = reinterpret_cast<const float4*>(smem + SM_CB);

    const int ql = lane & 3;      // quad lane -> column group
    const int qr = lane >> 2;     // row within 8-row group

    // ---- register-resident Wg B-fragments (tile-invariant) ----
    uint32_t wgA0[4], wgA1[4], wgB0[4], wgB1[4];
    {
        const float* WGAf = reinterpret_cast<const float*>(smem + SM_WGA);
        const float* WGBf = reinterpret_cast<const float*>(smem + SM_WGB);
        const int e4 = qr & 3;
        #pragma unroll
        for (int kt = 0; kt < 4; kt++) {
            int d0 = kt * 16 + 2 * ql;
            wgA0[kt] = pack_bf2(WGAf[d0 * 4 + e4],       WGAf[(d0 + 1) * 4 + e4]);
            wgA1[kt] = pack_bf2(WGAf[(d0 + 8) * 4 + e4], WGAf[(d0 + 9) * 4 + e4]);
            wgB0[kt] = pack_bf2(WGBf[d0 * 4 + e4],       WGBf[(d0 + 1) * 4 + e4]);
            wgB1[kt] = pack_bf2(WGBf[(d0 + 8) * 4 + e4], WGBf[(d0 + 9) * 4 + e4]);
        }
    }

    for (int tile = blockIdx.x; tile < ntiles; tile += gridDim.x) {
        const size_t tokbase = (size_t)tile * MT;

        // ---- X fragments straight from gmem ----
        uint32_t xf[2][4][4];
        #pragma unroll
        for (int m = 0; m < 2; m++) {
            const size_t r = tokbase + (size_t)(rbase + m * 16 + qr);
            const float* xr0 = x + r * 64;
            const float* xr8 = xr0 + 8 * 64;
            #pragma unroll
            for (int kt = 0; kt < 4; kt++) {
                const int c0 = kt * 16 + ql * 2;
                float2 f0 = *reinterpret_cast<const float2*>(xr0 + c0);
                float2 f1 = *reinterpret_cast<const float2*>(xr8 + c0);
                float2 f2 = *reinterpret_cast<const float2*>(xr0 + c0 + 8);
                float2 f3 = *reinterpret_cast<const float2*>(xr8 + c0 + 8);
                xf[m][kt][0] = pack_bf2(f0.x, f0.y);
                xf[m][kt][1] = pack_bf2(f1.x, f1.y);
                xf[m][kt][2] = pack_bf2(f2.x, f2.y);
                xf[m][kt][3] = pack_bf2(f3.x, f3.y);
            }
        }

        // ---- gates A on tensor core ----
        float4 gAf[2][2];
        uint32_t gA2[4][2][2];
        {
            float4 gf[2]; uint32_t g2c[4][2];
            #pragma unroll
            for (int m = 0; m < 2; m++) {
                gates_from_frags(xf[m], wgA0, wgA1, ql, gf, g2c);
                gAf[m][0] = gf[0]; gAf[m][1] = gf[1];
                #pragma unroll
                for (int e = 0; e < 4; e++) {
                    gA2[e][m][0] = g2c[e][0]; gA2[e][m][1] = g2c[e][1];
                }
            }
        }

        // ---- layer A: acc init = -sum_e g_e c_a (bias), then GEMM ----
        float acc[2][8][4];
        #pragma unroll
        for (int m = 0; m < 2; m++)
            #pragma unroll
            for (int n = 0; n < 8; n++) {
                int c = n * 8 + ql * 2;
                float4 c0 = CA4[c], c1 = CA4[c + 1];
                acc[m][n][0] = -dot4(gAf[m][0], c0);
                acc[m][n][1] = -dot4(gAf[m][0], c1);
                acc[m][n][2] = -dot4(gAf[m][1], c0);
                acc[m][n][3] = -dot4(gAf[m][1], c1);
            }

        run_layer(acc, xf, gA2, sb + SM_WA, lane);

        // ---- repack h: C-fragment layout == A-fragment layout (per kt) ----
        #pragma unroll
        for (int m = 0; m < 2; m++)
            #pragma unroll
            for (int kt = 0; kt < 4; kt++) {
                xf[m][kt][0] = pack_bf2(acc[m][2*kt][0],   acc[m][2*kt][1]);
                xf[m][kt][1] = pack_bf2(acc[m][2*kt][2],   acc[m][2*kt][3]);
                xf[m][kt][2] = pack_bf2(acc[m][2*kt+1][0], acc[m][2*kt+1][1]);
                xf[m][kt][3] = pack_bf2(acc[m][2*kt+1][2], acc[m][2*kt+1][3]);
            }

        // ---- prefetch next tile's x into L2 (16KB per CTA slice) ----
        if (tile + (int)gridDim.x < ntiles) {
            const char* p = reinterpret_cast<const char*>(
                x + (tokbase + (size_t)gridDim.x * MT + rbase) * 64) + lane * 256;
            asm volatile("prefetch.global.L2 [%0];" :: "l"(p));
            asm volatile("prefetch.global.L2 [%0];" :: "l"(p + 128));
        }

        // ---- gates B on tensor core ----
        float4 gBf[2][2];
        uint32_t gB2[4][2][2];
        {
            float4 gf[2]; uint32_t g2c[4][2];
            #pragma unroll
            for (int m = 0; m < 2; m++) {
                gates_from_frags(xf[m], wgB0, wgB1, ql, gf, g2c);
                gBf[m][0] = gf[0]; gBf[m][1] = gf[1];
                #pragma unroll
                for (int e = 0; e < 4; e++) {
                    gB2[e][m][0] = g2c[e][0]; gB2[e][m][1] = g2c[e][1];
                }
            }
        }

        // ---- layer B: acc init = x (residual) - sum_e g_e c_b, then GEMM ----
        #pragma unroll
        for (int m = 0; m < 2; m++) {
            const size_t rl = tokbase + (size_t)(rbase + m * 16 + qr);
            const size_t rh = rl + 8;
            #pragma unroll
            for (int n = 0; n < 8; n++) {
                int c = n * 8 + ql * 2;
                float4 c0 = CB4[c], c1 = CB4[c + 1];
                float2 xl = *reinterpret_cast<const float2*>(x + rl * 64 + c);
                float2 xh = *reinterpret_cast<const float2*>(x + rh * 64 + c);
                acc[m][n][0] = xl.x - dot4(gBf[m][0], c0);
                acc[m][n][1] = xl.y - dot4(gBf[m][0], c1);
                acc[m][n][2] = xh.x - dot4(gBf[m][1], c0);
                acc[m][n][3] = xh.y - dot4(gBf[m][1], c1);
            }
        }

        run_layer(acc, xf, gB2, sb + SM_WB, lane);

        // ---- epilogue: pure streaming stores ----
        #pragma unroll
        for (int m = 0; m < 2; m++) {
            const size_t rl = tokbase + (size_t)(rbase + m * 16 + qr);
            const size_t rh = rl + 8;
            #pragma unroll
            for (int n = 0; n < 8; n++) {
                int c = n * 8 + ql * 2;
                __stcs(reinterpret_cast<float2*>(out + rl * 64 + c),
                       make_float2(acc[m][n][0], acc[m][n][1]));
                __stcs(reinterpret_cast<float2*>(out + rh * 64 + c),
                       make_float2(acc[m][n][2], acc[m][n][3]));
            }
        }
    }
}

// ------------------------------- launch -----------------------------------

extern "C" void kernel_launch(void* const* d_in, const int* in_sizes, int n_in,
                              void* d_out, int out_size) {
    const float* x   = (const float*)d_in[0];
    const float* wga = (const float*)d_in[1];
    const float* wea = (const float*)d_in[2];
    const float* bea = (const float*)d_in[3];
    const float* wgb = (const float*)d_in[4];
    const float* web = (const float*)d_in[5];
    const float* beb = (const float*)d_in[6];
    float* out = (float*)d_out;

    const int ntok   = in_sizes[0] / 64;
    const int ntiles = ntok / MT;

    prep_kernel<<<64, 512>>>(wea, bea, web, beb);

    cudaFuncSetAttribute(moe_kernel, cudaFuncAttributeMaxDynamicSharedMemorySize, SMEM_TOTAL);
    int grid = ntiles < GRID ? ntiles : GRID;
    moe_kernel<<<grid, 256, SMEM_TOTAL>>>(x, wga, wgb, out, ntiles);
}

// round 8
// speedup vs baseline: 1.3568x; 1.3568x over previous
#include <cuda_runtime.h>
#include <cuda_bf16.h>
#include <cstdint>

// ---------------------------------------------------------------------------
// SPMoEAdaptor: out = moe_b(moe_a(x)) + x
//   moe(x) = sum_e softmax(x@Wg)[:,e] * ((x - b_e) @ W_e)
//          = sum_e (g_e * x) @ W_e  -  sum_e g_e * (b_e @ W_e)
// R7: revert to the R5 optimum geometry (128-thread CTAs, 3 CTAs/SM, ~168
// regs — R6 showed forcing 128 regs spills and regresses). New: dynamic
// per-warp work-stealing over 32-row units via a global atomic counter
// (reset by prep_kernel each launch) to eliminate the ragged-wave tail
// (~8% idle) and absorb L2-die throughput variance. Next-unit index is
// prefetched (pipelined atomic) so x L2-prefetch still works.
// ---------------------------------------------------------------------------

namespace {
// dynamic smem layout (bytes)
constexpr int SM_WA  = 0;               // 64 rows x 512B bf16 (layer A W^T, swizzled)
constexpr int SM_WB  = 32768;           // layer B weights
constexpr int SM_WGA = 65536;           // 64 x float4 (w_gate_a as [d][e])
constexpr int SM_WGB = 66560;
constexpr int SM_CA  = 67584;           // 64 x float4 (c_a as [f][e])
constexpr int SM_CB  = 68608;
constexpr int SMEM_TOTAL = 69632;       // 68KB -> 3 CTAs/SM

constexpr int GRID = 444;               // 148 SMs * 3 CTAs/SM
}

// device-global scratch (allocation-free rule)
// n-major: row f (0..63), 256 bf16 per row (k = e*64+d), chunk-XOR swizzled.
__device__ __align__(16) __nv_bfloat16 g_wswz[2][64 * 256];
__device__ __align__(16) float g_c[2][64 * 4];   // c[L][f*4+e] = (b_e @ W_e)[f]
__device__ unsigned g_unit_ctr;                  // work-stealing counter

// ------------------------------- helpers ----------------------------------

__device__ __forceinline__ uint32_t smem_u32(const void* p) {
    uint32_t a;
    asm("{ .reg .u64 t; cvta.to.shared.u64 t, %1; cvt.u32.u64 %0, t; }" : "=r"(a) : "l"(p));
    return a;
}

__device__ __forceinline__ void ldsm_x4(uint32_t* r, uint32_t addr) {
    asm volatile("ldmatrix.sync.aligned.m8n8.x4.shared.b16 {%0,%1,%2,%3}, [%4];"
                 : "=r"(r[0]), "=r"(r[1]), "=r"(r[2]), "=r"(r[3]) : "r"(addr));
}

__device__ __forceinline__ void mma_bf16(float* d, const uint32_t* a,
                                         uint32_t b0, uint32_t b1) {
    asm volatile("mma.sync.aligned.m16n8k16.row.col.f32.bf16.bf16.f32 "
                 "{%0,%1,%2,%3}, {%4,%5,%6,%7}, {%8,%9}, {%0,%1,%2,%3};"
                 : "+f"(d[0]), "+f"(d[1]), "+f"(d[2]), "+f"(d[3])
                 : "r"(a[0]), "r"(a[1]), "r"(a[2]), "r"(a[3]), "r"(b0), "r"(b1));
}

__device__ __forceinline__ uint32_t pack_bf2(float lo, float hi) {
    __nv_bfloat162 t = __floats2bfloat162_rn(lo, hi);
    return *reinterpret_cast<uint32_t*>(&t);
}

__device__ __forceinline__ uint32_t bf2bcast(float v) { return pack_bf2(v, v); }

__device__ __forceinline__ uint32_t hmul2u(uint32_t a, uint32_t b) {
    __nv_bfloat162 r = __hmul2(*reinterpret_cast<__nv_bfloat162*>(&a),
                               *reinterpret_cast<__nv_bfloat162*>(&b));
    return *reinterpret_cast<uint32_t*>(&r);
}

__device__ __forceinline__ float dot4(float4 a, float4 b) {
    return a.x * b.x + a.y * b.y + a.z * b.z + a.w * b.w;
}

__device__ __forceinline__ float4 softmax4(float4 l) {
    float mx = fmaxf(fmaxf(l.x, l.y), fmaxf(l.z, l.w));
    float e0 = __expf(l.x - mx), e1 = __expf(l.y - mx),
          e2 = __expf(l.z - mx), e3 = __expf(l.w - mx);
    float inv = 1.f / (e0 + e1 + e2 + e3);
    return make_float4(e0 * inv, e1 * inv, e2 * inv, e3 * inv);
}

// one MoE GEMM layer: acc[2][8][4] += sum over e,kt of (g_e o A_frag) @ W_frag
// Weights n-major: lane address = base + f_local*512 + ((e*8+kt*2+kh)^l7)*16
// + np*8192;  ldsm.x4 (non-trans) yields the mma.row.col B-fragments directly.
__device__ __forceinline__ void run_layer(float acc[2][8][4],
                                          const uint32_t xf[2][4][4],
                                          const uint32_t g2[4][2][2],
                                          uint32_t wbase, int lane) {
    const int l7 = lane & 7;
    const uint32_t lane_row = (uint32_t)(((lane >> 4) & 1) * 8 + l7);  // f within n16 grp
    const uint32_t kh = (uint32_t)((lane >> 3) & 1);                   // k-half
    const uint32_t lane_base = wbase + lane_row * 512u;
    #pragma unroll
    for (int e = 0; e < 4; e++) {
        #pragma unroll
        for (int kt = 0; kt < 4; kt++) {
            uint32_t a[2][4];
            #pragma unroll
            for (int m = 0; m < 2; m++) {
                a[m][0] = hmul2u(xf[m][kt][0], g2[e][m][0]);
                a[m][1] = hmul2u(xf[m][kt][1], g2[e][m][1]);
                a[m][2] = hmul2u(xf[m][kt][2], g2[e][m][0]);
                a[m][3] = hmul2u(xf[m][kt][3], g2[e][m][1]);
            }
            const uint32_t c0 = (uint32_t)(e * 8 + kt * 2) + kh;
            const uint32_t coff = ((c0 ^ (uint32_t)l7) << 4);
            #pragma unroll
            for (int np = 0; np < 4; np++) {
                uint32_t b[4];
                ldsm_x4(b, lane_base + (uint32_t)np * 8192u + coff);
                #pragma unroll
                for (int m = 0; m < 2; m++) {
                    mma_bf16(acc[m][2 * np],     a[m], b[0], b[1]);
                    mma_bf16(acc[m][2 * np + 1], a[m], b[2], b[3]);
                }
            }
        }
    }
}

// gates from A-fragments via tensor core: logits = frag @ Wg (Wg frags const).
// Output cols 0..3 = experts; cols 4..7 duplicate them, so a single
// shfl_xor(1) completes the per-row gather.
__device__ __forceinline__ void gates_from_frags(const uint32_t xf[4][4],
                                                 const uint32_t* wg0,
                                                 const uint32_t* wg1,
                                                 int ql,
                                                 float4 gf[2],
                                                 uint32_t g2[4][2]) {
    float l[4]  = {0.f, 0.f, 0.f, 0.f};
    float l2[4] = {0.f, 0.f, 0.f, 0.f};
    mma_bf16(l,  xf[0], wg0[0], wg1[0]);
    mma_bf16(l2, xf[1], wg0[1], wg1[1]);
    mma_bf16(l,  xf[2], wg0[2], wg1[2]);
    mma_bf16(l2, xf[3], wg0[3], wg1[3]);
    l[0] += l2[0]; l[1] += l2[1]; l[2] += l2[2]; l[3] += l2[3];
    float r0 = __shfl_xor_sync(0xffffffffu, l[0], 1);
    float r1 = __shfl_xor_sync(0xffffffffu, l[1], 1);
    float r2 = __shfl_xor_sync(0xffffffffu, l[2], 1);
    float r3 = __shfl_xor_sync(0xffffffffu, l[3], 1);
    bool even = (ql & 1) == 0;
    float4 La = even ? make_float4(l[0], l[1], r0, r1)
                     : make_float4(r0, r1, l[0], l[1]);
    float4 Lb = even ? make_float4(l[2], l[3], r2, r3)
                     : make_float4(r2, r3, l[2], l[3]);
    float4 ga = softmax4(La);
    float4 gb = softmax4(Lb);
    gf[0] = ga; gf[1] = gb;
    g2[0][0] = bf2bcast(ga.x); g2[1][0] = bf2bcast(ga.y);
    g2[2][0] = bf2bcast(ga.z); g2[3][0] = bf2bcast(ga.w);
    g2[0][1] = bf2bcast(gb.x); g2[1][1] = bf2bcast(gb.y);
    g2[2][1] = bf2bcast(gb.z); g2[3][1] = bf2bcast(gb.w);
}

// ------------------------------- prep kernel ------------------------------

__global__ void prep_kernel(const float* __restrict__ wea, const float* __restrict__ bea,
                            const float* __restrict__ web, const float* __restrict__ beb) {
    int idx = blockIdx.x * blockDim.x + threadIdx.x;
    if (idx == 0) g_unit_ctr = 0;                   // reset work-stealing counter
    if (idx < 2 * 4 * 64 * 64) {
        int L = idx >> 14;
        int r = idx & 16383;
        int e = r >> 12;
        int d = (r >> 6) & 63;
        int f = r & 63;
        const float* w = L ? web : wea;
        float v = w[(e * 64 + d) * 64 + f];
        // n-major: row f, k = e*64+d; 16B chunk = e*8 + d/8, XOR-swizzled by f&7
        int chunk = (e * 8 + (d >> 3)) ^ (f & 7);
        g_wswz[L][f * 256 + chunk * 8 + (d & 7)] = __float2bfloat16(v);
    }
    if (idx < 2 * 4 * 64) {
        int L = idx >> 8;
        int e = (idx >> 6) & 3;
        int f = idx & 63;
        const float* w = L ? web : wea;
        const float* b = L ? beb : bea;
        float s = 0.f;
        for (int d = 0; d < 64; d++)
            s += b[e * 64 + d] * w[(e * 64 + d) * 64 + f];
        g_c[L][f * 4 + e] = s;
    }
}

// ------------------------------- main kernel ------------------------------

__global__ void __launch_bounds__(128, 3)
moe_kernel(const float* __restrict__ x,
           const float* __restrict__ wg_a,
           const float* __restrict__ wg_b,
           float* __restrict__ out,
           int nunits) {
    extern __shared__ char smem[];
    const uint32_t sb = smem_u32(smem);
    const int tid  = threadIdx.x;
    const int lane = tid & 31;

    // ---- one-time cooperative weight copies ----
    {
        const uint4* s0 = reinterpret_cast<const uint4*>(g_wswz[0]);
        const uint4* s1 = reinterpret_cast<const uint4*>(g_wswz[1]);
        uint4* dA = reinterpret_cast<uint4*>(smem + SM_WA);
        uint4* dB = reinterpret_cast<uint4*>(smem + SM_WB);
        #pragma unroll
        for (int i = tid; i < 2048; i += 128) { dA[i] = s0[i]; dB[i] = s1[i]; }
        float* wga_s = reinterpret_cast<float*>(smem + SM_WGA);
        float* wgb_s = reinterpret_cast<float*>(smem + SM_WGB);
        float* ca_s  = reinterpret_cast<float*>(smem + SM_CA);
        float* cb_s  = reinterpret_cast<float*>(smem + SM_CB);
        #pragma unroll
        for (int i = tid; i < 256; i += 128) {
            wga_s[i] = wg_a[i]; wgb_s[i] = wg_b[i];
            ca_s[i]  = g_c[0][i]; cb_s[i] = g_c[1][i];
        }
    }
    __syncthreads();

    const float4* CA4  = reinterpret_cast<const float4*>(smem + SM_CA);
    const float4* CB4  = reinterpret_cast<const float4*>(smem + SM_CB);

    const int ql = lane & 3;      // quad lane -> column group
    const int qr = lane >> 2;     // row within 8-row group

    // ---- register-resident Wg B-fragments (tile-invariant) ----
    uint32_t wgA0[4], wgA1[4], wgB0[4], wgB1[4];
    {
        const float* WGAf = reinterpret_cast<const float*>(smem + SM_WGA);
        const float* WGBf = reinterpret_cast<const float*>(smem + SM_WGB);
        const int e4 = qr & 3;
        #pragma unroll
        for (int kt = 0; kt < 4; kt++) {
            int d0 = kt * 16 + 2 * ql;
            wgA0[kt] = pack_bf2(WGAf[d0 * 4 + e4],       WGAf[(d0 + 1) * 4 + e4]);
            wgA1[kt] = pack_bf2(WGAf[(d0 + 8) * 4 + e4], WGAf[(d0 + 9) * 4 + e4]);
            wgB0[kt] = pack_bf2(WGBf[d0 * 4 + e4],       WGBf[(d0 + 1) * 4 + e4]);
            wgB1[kt] = pack_bf2(WGBf[(d0 + 8) * 4 + e4], WGBf[(d0 + 9) * 4 + e4]);
        }
    }

    // ---- dynamic per-warp work-stealing over 32-row units ----
    unsigned u;
    if (lane == 0) u = atomicAdd(&g_unit_ctr, 1u);
    u = __shfl_sync(0xffffffffu, u, 0);

    while (u < (unsigned)nunits) {
        // pull next unit early (pipelined atomic, hides 318-cyc latency)
        unsigned un;
        if (lane == 0) un = atomicAdd(&g_unit_ctr, 1u);
        un = __shfl_sync(0xffffffffu, un, 0);

        const size_t rowbase = (size_t)u * 32;

        // ---- X fragments straight from gmem ----
        uint32_t xf[2][4][4];
        #pragma unroll
        for (int m = 0; m < 2; m++) {
            const size_t r = rowbase + (size_t)(m * 16 + qr);
            const float* xr0 = x + r * 64;
            const float* xr8 = xr0 + 8 * 64;
            #pragma unroll
            for (int kt = 0; kt < 4; kt++) {
                const int c0 = kt * 16 + ql * 2;
                float2 f0 = *reinterpret_cast<const float2*>(xr0 + c0);
                float2 f1 = *reinterpret_cast<const float2*>(xr8 + c0);
                float2 f2 = *reinterpret_cast<const float2*>(xr0 + c0 + 8);
                float2 f3 = *reinterpret_cast<const float2*>(xr8 + c0 + 8);
                xf[m][kt][0] = pack_bf2(f0.x, f0.y);
                xf[m][kt][1] = pack_bf2(f1.x, f1.y);
                xf[m][kt][2] = pack_bf2(f2.x, f2.y);
                xf[m][kt][3] = pack_bf2(f3.x, f3.y);
            }
        }

        // ---- prefetch next unit's x into L2 (8KB per warp) ----
        if (un < (unsigned)nunits) {
            const char* p = reinterpret_cast<const char*>(x + (size_t)un * 32 * 64)
                          + lane * 256;
            asm volatile("prefetch.global.L2 [%0];" :: "l"(p));
            asm volatile("prefetch.global.L2 [%0];" :: "l"(p + 128));
        }

        // ---- gates A on tensor core ----
        float4 gAf[2][2];
        uint32_t gA2[4][2][2];
        {
            float4 gf[2]; uint32_t g2c[4][2];
            #pragma unroll
            for (int m = 0; m < 2; m++) {
                gates_from_frags(xf[m], wgA0, wgA1, ql, gf, g2c);
                gAf[m][0] = gf[0]; gAf[m][1] = gf[1];
                #pragma unroll
                for (int e = 0; e < 4; e++) {
                    gA2[e][m][0] = g2c[e][0]; gA2[e][m][1] = g2c[e][1];
                }
            }
        }

        // ---- layer A: acc init = -sum_e g_e c_a (bias), then GEMM ----
        float acc[2][8][4];
        #pragma unroll
        for (int n = 0; n < 8; n++) {
            int c = n * 8 + ql * 2;
            float4 c0 = CA4[c], c1 = CA4[c + 1];
            #pragma unroll
            for (int m = 0; m < 2; m++) {
                acc[m][n][0] = -dot4(gAf[m][0], c0);
                acc[m][n][1] = -dot4(gAf[m][0], c1);
                acc[m][n][2] = -dot4(gAf[m][1], c0);
                acc[m][n][3] = -dot4(gAf[m][1], c1);
            }
        }

        run_layer(acc, xf, gA2, sb + SM_WA, lane);

        // ---- repack h: C-fragment layout == A-fragment layout (per kt) ----
        #pragma unroll
        for (int m = 0; m < 2; m++)
            #pragma unroll
            for (int kt = 0; kt < 4; kt++) {
                xf[m][kt][0] = pack_bf2(acc[m][2*kt][0],   acc[m][2*kt][1]);
                xf[m][kt][1] = pack_bf2(acc[m][2*kt][2],   acc[m][2*kt][3]);
                xf[m][kt][2] = pack_bf2(acc[m][2*kt+1][0], acc[m][2*kt+1][1]);
                xf[m][kt][3] = pack_bf2(acc[m][2*kt+1][2], acc[m][2*kt+1][3]);
            }

        // ---- gates B on tensor core ----
        float4 gBf[2][2];
        uint32_t gB2[4][2][2];
        {
            float4 gf[2]; uint32_t g2c[4][2];
            #pragma unroll
            for (int m = 0; m < 2; m++) {
                gates_from_frags(xf[m], wgB0, wgB1, ql, gf, g2c);
                gBf[m][0] = gf[0]; gBf[m][1] = gf[1];
                #pragma unroll
                for (int e = 0; e < 4; e++) {
                    gB2[e][m][0] = g2c[e][0]; gB2[e][m][1] = g2c[e][1];
                }
            }
        }

        // ---- layer B: acc init = x (residual) - sum_e g_e c_b, then GEMM ----
        #pragma unroll
        for (int n = 0; n < 8; n++) {
            int c = n * 8 + ql * 2;
            float4 c0 = CB4[c], c1 = CB4[c + 1];
            #pragma unroll
            for (int m = 0; m < 2; m++) {
                const size_t rl = rowbase + (size_t)(m * 16 + qr);
                const size_t rh = rl + 8;
                float2 xl = *reinterpret_cast<const float2*>(x + rl * 64 + c);
                float2 xh = *reinterpret_cast<const float2*>(x + rh * 64 + c);
                acc[m][n][0] = xl.x - dot4(gBf[m][0], c0);
                acc[m][n][1] = xl.y - dot4(gBf[m][0], c1);
                acc[m][n][2] = xh.x - dot4(gBf[m][1], c0);
                acc[m][n][3] = xh.y - dot4(gBf[m][1], c1);
            }
        }

        run_layer(acc, xf, gB2, sb + SM_WB, lane);

        // ---- epilogue: pure streaming stores ----
        #pragma unroll
        for (int m = 0; m < 2; m++) {
            const size_t rl = rowbase + (size_t)(m * 16 + qr);
            const size_t rh = rl + 8;
            #pragma unroll
            for (int n = 0; n < 8; n++) {
                int c = n * 8 + ql * 2;
                __stcs(reinterpret_cast<float2*>(out + rl * 64 + c),
                       make_float2(acc[m][n][0], acc[m][n][1]));
                __stcs(reinterpret_cast<float2*>(out + rh * 64 + c),
                       make_float2(acc[m][n][2], acc[m][n][3]));
            }
        }

        u = un;
    }
}

// ------------------------------- launch -----------------------------------

extern "C" void kernel_launch(void* const* d_in, const int* in_sizes, int n_in,
                              void* d_out, int out_size) {
    const float* x   = (const float*)d_in[0];
    const float* wga = (const float*)d_in[1];
    const float* wea = (const float*)d_in[2];
    const float* bea = (const float*)d_in[3];
    const float* wgb = (const float*)d_in[4];
    const float* web = (const float*)d_in[5];
    const float* beb = (const float*)d_in[6];
    float* out = (float*)d_out;

    const int ntok   = in_sizes[0] / 64;
    const int nunits = ntok / 32;

    prep_kernel<<<64, 512>>>(wea, bea, web, beb);

    cudaFuncSetAttribute(moe_kernel, cudaFuncAttributeMaxDynamicSharedMemorySize, SMEM_TOTAL);
    moe_kernel<<<GRID, 128, SMEM_TOTAL>>>(x, wga, wgb, out, nunits);
}